// round 13
// baseline (speedup 1.0000x reference)
#include <cuda_runtime.h>
#include <cuda_fp16.h>
#include <cstdint>
#include <cstddef>

#define D_MODEL 2048
#define N_HEADS 16
#define D_HEAD  128
#define RANK    32
#define BATCH   2
#define SEQ     2048
#define M_TOT   (BATCH*SEQ)        // 4096
#define N_QKV   (3*N_HEADS*RANK)   // 1536
#define K_FOLD  (N_HEADS*RANK)     // 512

// ---------------- device scratch (no allocations allowed) ----------------
__device__ __half g_Bqkv[(size_t)N_QKV * D_MODEL];   // [1536][2048] K-major fp16
__device__ __half g_Bo[(size_t)D_MODEL * K_FOLD];    // [2048][512]  K-major fp16
__device__ __half g_xc[(size_t)M_TOT * D_MODEL];     // fp16 x
__device__ __half g_qr[(size_t)BATCH * N_HEADS * SEQ * RANK];   // [bh][seq][r] (pre-scaled)
__device__ __half g_kr[(size_t)BATCH * N_HEADS * SEQ * RANK];   // [bh][seq][r]
__device__ __half g_vrT[(size_t)BATCH * N_HEADS * RANK * SEQ];  // [bh][r][seq]
__device__ __half g_yr[(size_t)M_TOT * K_FOLD];      // [4096][512] fp16

// ---------------- helpers -------------------------------------------------
__device__ __forceinline__ uint32_t smem_u32(const void* p) {
    uint32_t a;
    asm("{ .reg .u64 t; cvta.to.shared.u64 t, %1; cvt.u32.u64 %0, t; }"
        : "=r"(a) : "l"(p));
    return a;
}

__device__ __forceinline__ void cp_async16(uint32_t saddr, const void* gaddr) {
    asm volatile("cp.async.cg.shared.global [%0], [%1], 16;"
                 :: "r"(saddr), "l"(gaddr));
}
#define CP_COMMIT()  asm volatile("cp.async.commit_group;" ::: "memory")
#define CP_WAIT(n)   asm volatile("cp.async.wait_group %0;" :: "n"(n) : "memory")

// fp16 mma m16n8k16 row.col, fp32 accumulate
__device__ __forceinline__ void mma_f16(float* c, const uint32_t* a, const uint32_t* b) {
    asm volatile(
        "mma.sync.aligned.m16n8k16.row.col.f32.f16.f16.f32 "
        "{%0,%1,%2,%3}, {%4,%5,%6,%7}, {%8,%9}, {%0,%1,%2,%3};"
        : "+f"(c[0]), "+f"(c[1]), "+f"(c[2]), "+f"(c[3])
        : "r"(a[0]), "r"(a[1]), "r"(a[2]), "r"(a[3]), "r"(b[0]), "r"(b[1]));
}

__device__ __forceinline__ uint32_t pack_h2(float a, float b) {
    __half2 h = __floats2half2_rn(a, b);
    return *(uint32_t*)&h;
}

// packed fp16x2 exp2 — one MUFU op for two elements
__device__ __forceinline__ uint32_t ex2_h2(uint32_t h2in) {
    uint32_t r;
    asm("ex2.approx.f16x2 %0, %1;" : "=r"(r) : "r"(h2in));
    return r;
}

// (1/sqrt(32)) * log2(e) — folded into q at the GEMM1 epilogue
#define SC2F 0.25503837897544185f

// ---------------- fused prep: convert x + fold weights --------------------
#define PREP_CONV_BLKS 4096
#define PREP_QKV_BLKS  384
#define PREP_OUT_BLKS  128
#define PREP_BLKS (PREP_CONV_BLKS + PREP_QKV_BLKS + PREP_OUT_BLKS)

__global__ void __launch_bounds__(256)
prep_kernel(const float* __restrict__ x,
            const float* __restrict__ Wq, const float* __restrict__ Wk,
            const float* __restrict__ Wv, const float* __restrict__ Wo,
            const float* __restrict__ Wdown, const float* __restrict__ Wup) {
    __shared__ float sW[D_HEAD * RANK];   // 16 KB, used by fold tasks
    int tid = threadIdx.x;
    int bid = blockIdx.x;

    if (bid < PREP_CONV_BLKS) {
        // ---- convert x to fp16 ----
        int i = bid * 256 + tid;          // uint4 index
        const float4* xf = (const float4*)x;
        float4 v0 = xf[i * 2], v1 = xf[i * 2 + 1];
        uint4 o;
        o.x = pack_h2(v0.x, v0.y); o.y = pack_h2(v0.z, v0.w);
        o.z = pack_h2(v1.x, v1.y); o.w = pack_h2(v1.z, v1.w);
        ((uint4*)g_xc)[i] = o;
        return;
    }

    if (bid < PREP_CONV_BLKS + PREP_QKV_BLKS) {
        // ---- fold Wq/Wk/Wv with Wdown (K-major out, fp16) ----
        int b2 = bid - PREP_CONV_BLKS;
        int w  = b2 >> 7;                 // 0..2
        int h  = (b2 >> 3) & 15;
        int d  = (b2 & 7) * 256 + tid;

        for (int i = tid; i < D_HEAD*RANK/4; i += 256)
            ((float4*)sW)[i] = ((const float4*)Wdown)[i];
        __syncthreads();

        const float* W = (w == 0) ? Wq : (w == 1) ? Wk : Wv;
        const float* wp = W + (size_t)h * D_HEAD * D_MODEL + d;

        float acc[RANK];
#pragma unroll
        for (int r = 0; r < RANK; r++) acc[r] = 0.f;
#pragma unroll 4
        for (int i = 0; i < D_HEAD; i++) {
            float wv = wp[(size_t)i * D_MODEL];
#pragma unroll
            for (int r = 0; r < RANK; r++) acc[r] += wv * sW[i * RANK + r];
        }
#pragma unroll
        for (int r = 0; r < RANK; r++)
            g_Bqkv[(size_t)(w * K_FOLD + h * RANK + r) * D_MODEL + d] = __float2half_rn(acc[r]);
        return;
    }

    {
        // ---- fold Wup with Wo (K-major out [j][h*32+r], fp16) ----
        int b3 = bid - PREP_CONV_BLKS - PREP_QKV_BLKS;
        int h  = b3 >> 3;
        int j  = (b3 & 7) * 256 + tid;

        for (int i = tid; i < RANK*D_HEAD/4; i += 256)
            ((float4*)sW)[i] = ((const float4*)Wup)[i];
        __syncthreads();

        const float* wop = Wo + (size_t)j * D_MODEL + h * D_HEAD;

        float acc[RANK];
#pragma unroll
        for (int r = 0; r < RANK; r++) acc[r] = 0.f;
#pragma unroll 2
        for (int i = 0; i < D_HEAD; i += 4) {
            float4 w4 = *(const float4*)(wop + i);
#pragma unroll
            for (int r = 0; r < RANK; r++)
                acc[r] += w4.x * sW[r * D_HEAD + i]     + w4.y * sW[r * D_HEAD + i + 1]
                        + w4.z * sW[r * D_HEAD + i + 2] + w4.w * sW[r * D_HEAD + i + 3];
        }
#pragma unroll
        for (int r = 0; r < RANK; r++)
            g_Bo[(size_t)j * K_FOLD + h * RANK + r] = __float2half_rn(acc[r]);
    }
}

// ---------------- fp16 mma.sync GEMM (4 warps, 64x64 warp tiles) ----------
#define SSTR_U 36                             // b32 units per smem row (32 data)
#define ABUF_U (128 * SSTR_U)                 // 4608
#define STAGE_U (2 * ABUF_U)                  // 9216
#define GSTAGES 3
#define SMEM_BYTES (GSTAGES * STAGE_U * 4)    // 110592

template <int EPI>
__global__ void __launch_bounds__(128, 2)
gemm_mma(const __half* __restrict__ A, const __half* __restrict__ B,
         float* __restrict__ C, int N, int K) {
    extern __shared__ uint32_t smem_u[];
    uint32_t sbase = smem_u32(smem_u);

    int tid = threadIdx.x;
    int lane = tid & 31, wid = tid >> 5;
    int g = lane >> 2, t = lane & 3;
    int wm = (wid >> 1) * 64;
    int wn = (wid & 1) * 64;
    int m0 = blockIdx.y * 128;
    int n0 = blockIdx.x * 128;

    const __half* ga[8];
    const __half* gb[8];
    uint32_t sa_off[8], sb_off[8];
#pragma unroll
    for (int i = 0; i < 8; i++) {
        int idx = tid + i * 128;
        int r  = idx >> 3;
        int c4 = idx & 7;
        ga[i] = A + (size_t)(m0 + r) * K + c4 * 8;
        gb[i] = B + (size_t)(n0 + r) * K + c4 * 8;
        sa_off[i] = (uint32_t)((r * SSTR_U + c4 * 4) * 4);
        sb_off[i] = (uint32_t)((ABUF_U + r * SSTR_U + c4 * 4) * 4);
    }

    float acc[4][8][4];
#pragma unroll
    for (int mt = 0; mt < 4; mt++)
#pragma unroll
        for (int nt = 0; nt < 8; nt++)
#pragma unroll
            for (int e = 0; e < 4; e++) acc[mt][nt][e] = 0.f;

    int nk = K >> 6;   // K chunks of 64

#pragma unroll
    for (int s = 0; s < 2; s++) {
        uint32_t bofs = sbase + s * (STAGE_U * 4);
        const int ko = s * 64;
#pragma unroll
        for (int i = 0; i < 8; i++) {
            cp_async16(bofs + sa_off[i], ga[i] + ko);
            cp_async16(bofs + sb_off[i], gb[i] + ko);
        }
        CP_COMMIT();
    }

    int cur = 0, pre = 2;
    for (int kc = 0; kc < nk; kc++) {
        if (kc + 1 < nk) { CP_WAIT(1); } else { CP_WAIT(0); }
        __syncthreads();

        if (kc + 2 < nk) {
            uint32_t bofs = sbase + pre * (STAGE_U * 4);
            const int ko = (kc + 2) * 64;
#pragma unroll
            for (int i = 0; i < 8; i++) {
                cp_async16(bofs + sa_off[i], ga[i] + ko);
                cp_async16(bofs + sb_off[i], gb[i] + ko);
            }
            CP_COMMIT();
        }

        const uint32_t* sA = smem_u + cur * STAGE_U;
        const uint32_t* sB = sA + ABUF_U;

#pragma unroll
        for (int ks = 0; ks < 4; ks++) {      // 4 x k16
            int p0 = ks * 8;
            uint32_t a[4][4], b[8][2];
#pragma unroll
            for (int mt = 0; mt < 4; mt++) {
                const uint32_t* p = sA + (wm + mt * 16 + g) * SSTR_U + p0 + t;
                a[mt][0] = p[0];
                a[mt][1] = p[8 * SSTR_U];
                a[mt][2] = p[4];
                a[mt][3] = p[8 * SSTR_U + 4];
            }
#pragma unroll
            for (int nt = 0; nt < 8; nt++) {
                const uint32_t* p = sB + (wn + nt * 8 + g) * SSTR_U + p0 + t;
                b[nt][0] = p[0];
                b[nt][1] = p[4];
            }
#pragma unroll
            for (int mt = 0; mt < 4; mt++)
#pragma unroll
                for (int nt = 0; nt < 8; nt++)
                    mma_f16(acc[mt][nt], a[mt], b[nt]);
        }
        cur = (cur == GSTAGES - 1) ? 0 : cur + 1;
        pre = (pre == GSTAGES - 1) ? 0 : pre + 1;
    }

#pragma unroll
    for (int mt = 0; mt < 4; mt++) {
        int r0 = m0 + wm + mt * 16 + g;
#pragma unroll
        for (int nt = 0; nt < 8; nt++) {
            int cn = n0 + wn + nt * 8 + t * 2;
            if (EPI == 0) {
                *(float2*)(C + (size_t)r0 * N + cn) =
                    make_float2(acc[mt][nt][0], acc[mt][nt][1]);
                *(float2*)(C + (size_t)(r0 + 8) * N + cn) =
                    make_float2(acc[mt][nt][2], acc[mt][nt][3]);
            } else {
                // scatter q/k/v as fp16 (q pre-scaled by SC2F; V transposed)
                int w = cn >> 9;
                int h = (cn >> 5) & 15;
                int r = cn & 31;
#pragma unroll
                for (int lh = 0; lh < 2; lh++) {
                    int rr = r0 + lh * 8;
                    int b0 = rr >> 11, t0 = rr & 2047;
                    float v0 = acc[mt][nt][lh * 2], v1 = acc[mt][nt][lh * 2 + 1];
                    if (w == 2) {
                        __half* vp = g_vrT + ((size_t)(b0 * N_HEADS + h) * RANK) * SEQ + t0;
                        vp[(size_t)r * SEQ]       = __float2half_rn(v0);
                        vp[(size_t)(r + 1) * SEQ] = __float2half_rn(v1);
                    } else {
                        if (w == 0) { v0 *= SC2F; v1 *= SC2F; }
                        __half* basep = (w == 0) ? g_qr : g_kr;
                        uint32_t hv = pack_h2(v0, v1);
                        *(uint32_t*)(basep + ((size_t)(b0 * N_HEADS + h) * SEQ + t0) * RANK + r) = hv;
                    }
                }
            }
        }
    }
}

// ---------------- fp16 tensor-core flash attention in rank space ----------
// 256 threads / 8 warps, 16 q-rows per warp: doubles warps/SMSP (2->4) to
// hide the serial S-mma -> exp2 -> PV-mma dependency chain. Fixed-shift
// softmax + f16x2 exp2 + register P-fragment reuse, arithmetic unchanged.
#define TQ   128
#define TK   64
#define NKT  (SEQ/TK)       // 32
#define KSTR_U 20           // K row: 16 b32 data (32 halves)
#define VSTR_U 36           // V_T row: 32 b32 data (64 halves)
#define QSTG_U (128*KSTR_U) // 2560 (Q staging)
#define AKV_OFF QSTG_U
#define AKSZ_U (TK*KSTR_U)  // 1280
#define AVSZ_U (32*VSTR_U)  // 1152
#define ASTG_U (AKSZ_U+AVSZ_U)  // 2432
#define ASTAGES 3
#define ASMEM_BYTES ((AKV_OFF + ASTAGES*ASTG_U)*4)   // 39424

__device__ __forceinline__ void prefetch_kv(uint32_t sbase, int stage,
                                            const __half* Kb, const __half* VTb,
                                            int kt, int tid) {
    uint32_t koff = sbase + (AKV_OFF + stage * ASTG_U) * 4;
    uint32_t voff = koff + AKSZ_U * 4;
    const __half* kp = Kb + (size_t)kt * TK * RANK;
    const __half* vp = VTb + kt * TK;
    {   // K: 64 rows x 4 chunks = 256 (one per thread)
        int r = tid >> 2, c4 = tid & 3;
        cp_async16(koff + (r * KSTR_U + c4 * 4) * 4, kp + r * RANK + c4 * 8);
    }
    {   // V_T: 32 rows x 8 chunks = 256 (one per thread)
        int r = tid >> 3, c4 = tid & 7;
        cp_async16(voff + (r * VSTR_U + c4 * 4) * 4, vp + (size_t)r * SEQ + c4 * 8);
    }
    CP_COMMIT();
}

__global__ void __launch_bounds__(256, 2)
attn_mma() {
    extern __shared__ uint32_t asmem[];
    uint32_t sbase = smem_u32(asmem);
    int tid = threadIdx.x;
    int lane = tid & 31, wid = tid >> 5;     // 8 warps
    int g = lane >> 2, t = lane & 3;
    int bh = blockIdx.y;
    int q0 = blockIdx.x * TQ;
    int wq = wid * 16;                        // 16 q-rows per warp

    const __half* Qb  = g_qr + ((size_t)bh * SEQ + q0) * RANK;
    const __half* Kb  = g_kr + (size_t)bh * SEQ * RANK;
    const __half* VTb = g_vrT + (size_t)bh * RANK * SEQ;

    prefetch_kv(sbase, 0, Kb, VTb, 0, tid);
    prefetch_kv(sbase, 1, Kb, VTb, 1, tid);

    // stage Q into its own region (128 rows x 4 chunks = 512, 2 per thread)
#pragma unroll
    for (int j = 0; j < 2; j++) {
        int idx = tid + j * 256;
        int r = idx >> 2, c4 = idx & 3;
        *(uint4*)(asmem + r * KSTR_U + c4 * 4) = *(const uint4*)(Qb + r * RANK + c4 * 8);
    }
    __syncthreads();

    uint32_t qf[2][4];   // [k16-step][frag]
#pragma unroll
    for (int ks = 0; ks < 2; ks++) {
        const uint32_t* p = asmem + (wq + g) * KSTR_U + ks * 8 + t;
        qf[ks][0] = p[0];
        qf[ks][1] = p[8 * KSTR_U];
        qf[ks][2] = p[4];
        qf[ks][3] = p[8 * KSTR_U + 4];
    }

    float l[2];
    float oacc[4][4];
    l[0] = l[1] = 0.f;
#pragma unroll
    for (int nt = 0; nt < 4; nt++)
#pragma unroll
        for (int e = 0; e < 4; e++) oacc[nt][e] = 0.f;

    int cur = 0, pre = 2;
    for (int kt = 0; kt < NKT; kt++) {
        if (kt + 1 < NKT) { CP_WAIT(1); } else { CP_WAIT(0); }
        __syncthreads();

        if (kt + 2 < NKT) prefetch_kv(sbase, pre, Kb, VTb, kt + 2, tid);

        const uint32_t* sKb = asmem + AKV_OFF + cur * ASTG_U;
        const uint32_t* sVb = sKb + AKSZ_U;

        // ---- S = Q K^T (q pre-scaled: S already in log2 domain) ----
        float sacc[8][4];
#pragma unroll
        for (int nt = 0; nt < 8; nt++)
#pragma unroll
            for (int e = 0; e < 4; e++) sacc[nt][e] = 0.f;
#pragma unroll
        for (int ks = 0; ks < 2; ks++) {
#pragma unroll
            for (int nt = 0; nt < 8; nt++) {
                const uint32_t* p = sKb + (nt * 8 + g) * KSTR_U + ks * 8 + t;
                uint32_t bk[2] = { p[0], p[4] };
                mma_f16(sacc[nt], qf[ks], bk);
            }
        }

        // ---- P = exp2(S) via packed f16x2 MUFU; result IS the PV A-frag ----
        uint32_t ph[8][2];
#pragma unroll
        for (int nt = 0; nt < 8; nt++) {
            // S rounded to fp16, exp2 in fp16x2; l sums the SAME fp16 P
            uint32_t s01 = pack_h2(sacc[nt][0], sacc[nt][1]);
            uint32_t s23 = pack_h2(sacc[nt][2], sacc[nt][3]);
            uint32_t p01 = ex2_h2(s01);
            uint32_t p23 = ex2_h2(s23);
            float2 f01 = __half22float2(*(__half2*)&p01);
            float2 f23 = __half22float2(*(__half2*)&p23);
            l[0] += f01.x + f01.y;
            l[1] += f23.x + f23.y;
            ph[nt][0] = p01;   // rows g,   cols 2t,2t+1
            ph[nt][1] = p23;   // rows g+8, cols 2t,2t+1
        }

        // ---- O += P V (A-frags straight from registers) ----
#pragma unroll
        for (int ks = 0; ks < 4; ks++) {
            uint32_t af[4] = { ph[2 * ks][0],     ph[2 * ks][1],
                               ph[2 * ks + 1][0], ph[2 * ks + 1][1] };
#pragma unroll
            for (int nt = 0; nt < 4; nt++) {
                const uint32_t* p = sVb + (nt * 8 + g) * VSTR_U + ks * 8 + t;
                uint32_t bf[2] = { p[0], p[4] };
                mma_f16(oacc[nt], af, bf);
            }
        }
        cur = (cur == ASTAGES - 1) ? 0 : cur + 1;
        pre = (pre == ASTAGES - 1) ? 0 : pre + 1;
    }

    // ---- epilogue: single l reduction, normalize, round fp16, store ----
#pragma unroll
    for (int i = 0; i < 2; i++) {
        l[i] += __shfl_xor_sync(0xffffffffu, l[i], 1);
        l[i] += __shfl_xor_sync(0xffffffffu, l[i], 2);
    }
    int b = bh >> 4, h = bh & 15;
#pragma unroll
    for (int lh = 0; lh < 2; lh++) {
        int row = q0 + wq + g + lh * 8;
        float inv = 1.f / l[lh];
        __half* yp = g_yr + ((size_t)(b * SEQ) + row) * K_FOLD + h * RANK;
#pragma unroll
        for (int nt = 0; nt < 4; nt++) {
            uint32_t hv = pack_h2(oacc[nt][lh * 2] * inv,
                                  oacc[nt][lh * 2 + 1] * inv);
            *(uint32_t*)(yp + nt * 8 + 2 * t) = hv;
        }
    }
}

// ---------------- launch --------------------------------------------------
extern "C" void kernel_launch(void* const* d_in, const int* in_sizes, int n_in,
                              void* d_out, int out_size) {
    const float* x     = (const float*)d_in[0];
    const float* Wq    = (const float*)d_in[1];
    const float* Wk    = (const float*)d_in[2];
    const float* Wv    = (const float*)d_in[3];
    const float* Wo    = (const float*)d_in[4];
    const float* Wdown = (const float*)d_in[5];
    const float* Wup   = (const float*)d_in[6];
    float* out = (float*)d_out;

    void *pBq, *pBo, *pXc, *pYr;
    cudaGetSymbolAddress(&pBq, g_Bqkv);
    cudaGetSymbolAddress(&pBo, g_Bo);
    cudaGetSymbolAddress(&pXc, g_xc);
    cudaGetSymbolAddress(&pYr, g_yr);

    static bool attr_done = false;
    if (!attr_done) {
        cudaFuncSetAttribute(gemm_mma<0>, cudaFuncAttributeMaxDynamicSharedMemorySize, SMEM_BYTES);
        cudaFuncSetAttribute(gemm_mma<1>, cudaFuncAttributeMaxDynamicSharedMemorySize, SMEM_BYTES);
        cudaFuncSetAttribute(attn_mma,    cudaFuncAttributeMaxDynamicSharedMemorySize, ASMEM_BYTES);
        attr_done = true;
    }

    // fused prep: convert x + fold weights (one launch, independent blocks)
    prep_kernel<<<PREP_BLKS, 256>>>(x, Wq, Wk, Wv, Wo, Wdown, Wup);

    // q_r/k_r/v_r = x @ A_qkv  (fp16 mma.sync, scatter epilogue; q pre-scaled)
    gemm_mma<1><<<dim3(N_QKV/128, M_TOT/128), 128, SMEM_BYTES>>>(
        (const __half*)pXc, (const __half*)pBq, nullptr, N_QKV, D_MODEL);

    // rank-space fp16 tensor-core flash attention -> g_yr [4096, 512]
    attn_mma<<<dim3(SEQ/TQ, BATCH*N_HEADS), 256, ASMEM_BYTES>>>();

    // out = y_r @ B_o  (fp16 mma.sync)
    gemm_mma<0><<<dim3(D_MODEL/128, M_TOT/128), 128, SMEM_BYTES>>>(
        (const __half*)pYr, (const __half*)pBo, out, D_MODEL, K_FOLD);
}

// round 14
// speedup vs baseline: 1.0203x; 1.0203x over previous
#include <cuda_runtime.h>
#include <cuda_fp16.h>
#include <cstdint>
#include <cstddef>

#define D_MODEL 2048
#define N_HEADS 16
#define D_HEAD  128
#define RANK    32
#define BATCH   2
#define SEQ     2048
#define M_TOT   (BATCH*SEQ)        // 4096
#define N_QKV   (3*N_HEADS*RANK)   // 1536
#define K_FOLD  (N_HEADS*RANK)     // 512

// ---------------- device scratch (no allocations allowed) ----------------
__device__ __half g_Bqkv[(size_t)N_QKV * D_MODEL];   // [1536][2048] K-major fp16
__device__ __half g_Bo[(size_t)D_MODEL * K_FOLD];    // [2048][512]  K-major fp16
__device__ __half g_xc[(size_t)M_TOT * D_MODEL];     // fp16 x
__device__ __half g_qr[(size_t)BATCH * N_HEADS * SEQ * RANK];   // [bh][seq][r] (pre-scaled)
__device__ __half g_kr[(size_t)BATCH * N_HEADS * SEQ * RANK];   // [bh][seq][r]
__device__ __half g_vrT[(size_t)BATCH * N_HEADS * RANK * SEQ];  // [bh][r][seq]
__device__ __half g_yr[(size_t)M_TOT * K_FOLD];      // [4096][512] fp16

// ---------------- helpers -------------------------------------------------
__device__ __forceinline__ uint32_t smem_u32(const void* p) {
    uint32_t a;
    asm("{ .reg .u64 t; cvta.to.shared.u64 t, %1; cvt.u32.u64 %0, t; }"
        : "=r"(a) : "l"(p));
    return a;
}

__device__ __forceinline__ void cp_async16(uint32_t saddr, const void* gaddr) {
    asm volatile("cp.async.cg.shared.global [%0], [%1], 16;"
                 :: "r"(saddr), "l"(gaddr));
}
#define CP_COMMIT()  asm volatile("cp.async.commit_group;" ::: "memory")
#define CP_WAIT(n)   asm volatile("cp.async.wait_group %0;" :: "n"(n) : "memory")

// fp16 mma m16n8k16 row.col, fp32 accumulate
__device__ __forceinline__ void mma_f16(float* c, const uint32_t* a, const uint32_t* b) {
    asm volatile(
        "mma.sync.aligned.m16n8k16.row.col.f32.f16.f16.f32 "
        "{%0,%1,%2,%3}, {%4,%5,%6,%7}, {%8,%9}, {%0,%1,%2,%3};"
        : "+f"(c[0]), "+f"(c[1]), "+f"(c[2]), "+f"(c[3])
        : "r"(a[0]), "r"(a[1]), "r"(a[2]), "r"(a[3]), "r"(b[0]), "r"(b[1]));
}

__device__ __forceinline__ uint32_t pack_h2(float a, float b) {
    __half2 h = __floats2half2_rn(a, b);
    return *(uint32_t*)&h;
}

// packed fp16x2 exp2 — one MUFU op for two elements
__device__ __forceinline__ uint32_t ex2_h2(uint32_t h2in) {
    uint32_t r;
    asm("ex2.approx.f16x2 %0, %1;" : "=r"(r) : "r"(h2in));
    return r;
}

// (1/sqrt(32)) * log2(e) — folded into q at the GEMM1 epilogue
#define SC2F 0.25503837897544185f

// ---------------- fused prep: convert x + fold weights --------------------
#define PREP_CONV_BLKS 4096
#define PREP_QKV_BLKS  384
#define PREP_OUT_BLKS  128
#define PREP_BLKS (PREP_CONV_BLKS + PREP_QKV_BLKS + PREP_OUT_BLKS)

__global__ void __launch_bounds__(256)
prep_kernel(const float* __restrict__ x,
            const float* __restrict__ Wq, const float* __restrict__ Wk,
            const float* __restrict__ Wv, const float* __restrict__ Wo,
            const float* __restrict__ Wdown, const float* __restrict__ Wup) {
    __shared__ float sW[D_HEAD * RANK];   // 16 KB, used by fold tasks
    int tid = threadIdx.x;
    int bid = blockIdx.x;

    if (bid < PREP_CONV_BLKS) {
        // ---- convert x to fp16 ----
        int i = bid * 256 + tid;          // uint4 index
        const float4* xf = (const float4*)x;
        float4 v0 = xf[i * 2], v1 = xf[i * 2 + 1];
        uint4 o;
        o.x = pack_h2(v0.x, v0.y); o.y = pack_h2(v0.z, v0.w);
        o.z = pack_h2(v1.x, v1.y); o.w = pack_h2(v1.z, v1.w);
        ((uint4*)g_xc)[i] = o;
        return;
    }

    if (bid < PREP_CONV_BLKS + PREP_QKV_BLKS) {
        // ---- fold Wq/Wk/Wv with Wdown (K-major out, fp16) ----
        int b2 = bid - PREP_CONV_BLKS;
        int w  = b2 >> 7;                 // 0..2
        int h  = (b2 >> 3) & 15;
        int d  = (b2 & 7) * 256 + tid;

        for (int i = tid; i < D_HEAD*RANK/4; i += 256)
            ((float4*)sW)[i] = ((const float4*)Wdown)[i];
        __syncthreads();

        const float* W = (w == 0) ? Wq : (w == 1) ? Wk : Wv;
        const float* wp = W + (size_t)h * D_HEAD * D_MODEL + d;

        float acc[RANK];
#pragma unroll
        for (int r = 0; r < RANK; r++) acc[r] = 0.f;
#pragma unroll 4
        for (int i = 0; i < D_HEAD; i++) {
            float wv = wp[(size_t)i * D_MODEL];
#pragma unroll
            for (int r = 0; r < RANK; r++) acc[r] += wv * sW[i * RANK + r];
        }
#pragma unroll
        for (int r = 0; r < RANK; r++)
            g_Bqkv[(size_t)(w * K_FOLD + h * RANK + r) * D_MODEL + d] = __float2half_rn(acc[r]);
        return;
    }

    {
        // ---- fold Wup with Wo (K-major out [j][h*32+r], fp16) ----
        int b3 = bid - PREP_CONV_BLKS - PREP_QKV_BLKS;
        int h  = b3 >> 3;
        int j  = (b3 & 7) * 256 + tid;

        for (int i = tid; i < RANK*D_HEAD/4; i += 256)
            ((float4*)sW)[i] = ((const float4*)Wup)[i];
        __syncthreads();

        const float* wop = Wo + (size_t)j * D_MODEL + h * D_HEAD;

        float acc[RANK];
#pragma unroll
        for (int r = 0; r < RANK; r++) acc[r] = 0.f;
#pragma unroll 2
        for (int i = 0; i < D_HEAD; i += 4) {
            float4 w4 = *(const float4*)(wop + i);
#pragma unroll
            for (int r = 0; r < RANK; r++)
                acc[r] += w4.x * sW[r * D_HEAD + i]     + w4.y * sW[r * D_HEAD + i + 1]
                        + w4.z * sW[r * D_HEAD + i + 2] + w4.w * sW[r * D_HEAD + i + 3];
        }
#pragma unroll
        for (int r = 0; r < RANK; r++)
            g_Bo[(size_t)j * K_FOLD + h * RANK + r] = __float2half_rn(acc[r]);
    }
}

// ---------------- fp16 mma.sync GEMM (4 warps, 64x64 warp tiles) ----------
#define SSTR_U 36                             // b32 units per smem row (32 data)
#define ABUF_U (128 * SSTR_U)                 // 4608
#define STAGE_U (2 * ABUF_U)                  // 9216
#define GSTAGES 3
#define SMEM_BYTES (GSTAGES * STAGE_U * 4)    // 110592

template <int EPI>
__global__ void __launch_bounds__(128, 2)
gemm_mma(const __half* __restrict__ A, const __half* __restrict__ B,
         float* __restrict__ C, int N, int K) {
    extern __shared__ uint32_t smem_u[];
    uint32_t sbase = smem_u32(smem_u);

    int tid = threadIdx.x;
    int lane = tid & 31, wid = tid >> 5;
    int g = lane >> 2, t = lane & 3;
    int wm = (wid >> 1) * 64;
    int wn = (wid & 1) * 64;
    int m0 = blockIdx.y * 128;
    int n0 = blockIdx.x * 128;

    const __half* ga[8];
    const __half* gb[8];
    uint32_t sa_off[8], sb_off[8];
#pragma unroll
    for (int i = 0; i < 8; i++) {
        int idx = tid + i * 128;
        int r  = idx >> 3;
        int c4 = idx & 7;
        ga[i] = A + (size_t)(m0 + r) * K + c4 * 8;
        gb[i] = B + (size_t)(n0 + r) * K + c4 * 8;
        sa_off[i] = (uint32_t)((r * SSTR_U + c4 * 4) * 4);
        sb_off[i] = (uint32_t)((ABUF_U + r * SSTR_U + c4 * 4) * 4);
    }

    float acc[4][8][4];
#pragma unroll
    for (int mt = 0; mt < 4; mt++)
#pragma unroll
        for (int nt = 0; nt < 8; nt++)
#pragma unroll
            for (int e = 0; e < 4; e++) acc[mt][nt][e] = 0.f;

    int nk = K >> 6;   // K chunks of 64

#pragma unroll
    for (int s = 0; s < 2; s++) {
        uint32_t bofs = sbase + s * (STAGE_U * 4);
        const int ko = s * 64;
#pragma unroll
        for (int i = 0; i < 8; i++) {
            cp_async16(bofs + sa_off[i], ga[i] + ko);
            cp_async16(bofs + sb_off[i], gb[i] + ko);
        }
        CP_COMMIT();
    }

    int cur = 0, pre = 2;
    for (int kc = 0; kc < nk; kc++) {
        if (kc + 1 < nk) { CP_WAIT(1); } else { CP_WAIT(0); }
        __syncthreads();

        if (kc + 2 < nk) {
            uint32_t bofs = sbase + pre * (STAGE_U * 4);
            const int ko = (kc + 2) * 64;
#pragma unroll
            for (int i = 0; i < 8; i++) {
                cp_async16(bofs + sa_off[i], ga[i] + ko);
                cp_async16(bofs + sb_off[i], gb[i] + ko);
            }
            CP_COMMIT();
        }

        const uint32_t* sA = smem_u + cur * STAGE_U;
        const uint32_t* sB = sA + ABUF_U;

#pragma unroll
        for (int ks = 0; ks < 4; ks++) {      // 4 x k16
            int p0 = ks * 8;
            uint32_t a[4][4], b[8][2];
#pragma unroll
            for (int mt = 0; mt < 4; mt++) {
                const uint32_t* p = sA + (wm + mt * 16 + g) * SSTR_U + p0 + t;
                a[mt][0] = p[0];
                a[mt][1] = p[8 * SSTR_U];
                a[mt][2] = p[4];
                a[mt][3] = p[8 * SSTR_U + 4];
            }
#pragma unroll
            for (int nt = 0; nt < 8; nt++) {
                const uint32_t* p = sB + (wn + nt * 8 + g) * SSTR_U + p0 + t;
                b[nt][0] = p[0];
                b[nt][1] = p[4];
            }
#pragma unroll
            for (int mt = 0; mt < 4; mt++)
#pragma unroll
                for (int nt = 0; nt < 8; nt++)
                    mma_f16(acc[mt][nt], a[mt], b[nt]);
        }
        cur = (cur == GSTAGES - 1) ? 0 : cur + 1;
        pre = (pre == GSTAGES - 1) ? 0 : pre + 1;
    }

#pragma unroll
    for (int mt = 0; mt < 4; mt++) {
        int r0 = m0 + wm + mt * 16 + g;
#pragma unroll
        for (int nt = 0; nt < 8; nt++) {
            int cn = n0 + wn + nt * 8 + t * 2;
            if (EPI == 0) {
                *(float2*)(C + (size_t)r0 * N + cn) =
                    make_float2(acc[mt][nt][0], acc[mt][nt][1]);
                *(float2*)(C + (size_t)(r0 + 8) * N + cn) =
                    make_float2(acc[mt][nt][2], acc[mt][nt][3]);
            } else {
                // scatter q/k/v as fp16 (q pre-scaled by SC2F; V transposed)
                int w = cn >> 9;
                int h = (cn >> 5) & 15;
                int r = cn & 31;
#pragma unroll
                for (int lh = 0; lh < 2; lh++) {
                    int rr = r0 + lh * 8;
                    int b0 = rr >> 11, t0 = rr & 2047;
                    float v0 = acc[mt][nt][lh * 2], v1 = acc[mt][nt][lh * 2 + 1];
                    if (w == 2) {
                        __half* vp = g_vrT + ((size_t)(b0 * N_HEADS + h) * RANK) * SEQ + t0;
                        vp[(size_t)r * SEQ]       = __float2half_rn(v0);
                        vp[(size_t)(r + 1) * SEQ] = __float2half_rn(v1);
                    } else {
                        if (w == 0) { v0 *= SC2F; v1 *= SC2F; }
                        __half* basep = (w == 0) ? g_qr : g_kr;
                        uint32_t hv = pack_h2(v0, v1);
                        *(uint32_t*)(basep + ((size_t)(b0 * N_HEADS + h) * SEQ + t0) * RANK + r) = hv;
                    }
                }
            }
        }
    }
}

// ---------------- fp16 tensor-core flash attention in rank space ----------
// R12 shape (128 thr, 32 q-rows/warp) + CROSS-TILE SOFTWARE PIPELINE:
// within one barrier window, S-mma of tile kt+1 is issued before PV-mma of
// tile kt (independent chains; sacc is drained into ph before reuse).
// 4-stage kv ring so V(kt) outlives the prefetch issued at kt+1's barrier.
#define TQ   128
#define TK   64
#define NKT  (SEQ/TK)       // 32
#define KSTR_U 20           // K row: 16 b32 data (32 halves)
#define VSTR_U 36           // V_T row: 32 b32 data (64 halves)
#define QSTG_U (128*KSTR_U) // 2560 (Q staging)
#define AKV_OFF QSTG_U
#define AKSZ_U (TK*KSTR_U)  // 1280
#define AVSZ_U (32*VSTR_U)  // 1152
#define ASTG_U (AKSZ_U+AVSZ_U)  // 2432
#define ASTAGES 4
#define ASMEM_BYTES ((AKV_OFF + ASTAGES*ASTG_U)*4)   // 49152

__device__ __forceinline__ void prefetch_kv(uint32_t sbase, int stage,
                                            const __half* Kb, const __half* VTb,
                                            int kt, int tid) {
    uint32_t koff = sbase + (AKV_OFF + stage * ASTG_U) * 4;
    uint32_t voff = koff + AKSZ_U * 4;
    const __half* kp = Kb + (size_t)kt * TK * RANK;
    const __half* vp = VTb + kt * TK;
#pragma unroll
    for (int j = 0; j < 2; j++) {           // K: 64 rows x 4 chunks = 256
        int idx = tid + j * 128;
        int r = idx >> 2, c4 = idx & 3;
        cp_async16(koff + (r * KSTR_U + c4 * 4) * 4, kp + r * RANK + c4 * 8);
    }
#pragma unroll
    for (int j = 0; j < 2; j++) {           // V_T: 32 rows x 8 chunks = 256
        int idx = tid + j * 128;
        int r = idx >> 3, c4 = idx & 7;
        cp_async16(voff + (r * VSTR_U + c4 * 4) * 4, vp + (size_t)r * SEQ + c4 * 8);
    }
    CP_COMMIT();
}

__device__ __forceinline__ void s_mma_tile(float sacc[2][8][4],
                                           const uint32_t qf[2][2][4],
                                           const uint32_t* sKb, int g, int t) {
#pragma unroll
    for (int mt = 0; mt < 2; mt++)
#pragma unroll
        for (int nt = 0; nt < 8; nt++)
#pragma unroll
            for (int e = 0; e < 4; e++) sacc[mt][nt][e] = 0.f;
#pragma unroll
    for (int ks = 0; ks < 2; ks++) {
        uint32_t bk[8][2];
#pragma unroll
        for (int nt = 0; nt < 8; nt++) {
            const uint32_t* p = sKb + (nt * 8 + g) * KSTR_U + ks * 8 + t;
            bk[nt][0] = p[0];
            bk[nt][1] = p[4];
        }
#pragma unroll
        for (int mt = 0; mt < 2; mt++)
#pragma unroll
            for (int nt = 0; nt < 8; nt++)
                mma_f16(sacc[mt][nt], qf[mt][ks], bk[nt]);
    }
}

__global__ void __launch_bounds__(128, 2)
attn_mma() {
    extern __shared__ uint32_t asmem[];
    uint32_t sbase = smem_u32(asmem);
    int tid = threadIdx.x;
    int lane = tid & 31, wid = tid >> 5;
    int g = lane >> 2, t = lane & 3;
    int bh = blockIdx.y;
    int q0 = blockIdx.x * TQ;
    int wq = wid * 32;

    const __half* Qb  = g_qr + ((size_t)bh * SEQ + q0) * RANK;
    const __half* Kb  = g_kr + (size_t)bh * SEQ * RANK;
    const __half* VTb = g_vrT + (size_t)bh * RANK * SEQ;

    prefetch_kv(sbase, 0, Kb, VTb, 0, tid);
    prefetch_kv(sbase, 1, Kb, VTb, 1, tid);
    prefetch_kv(sbase, 2, Kb, VTb, 2, tid);

    // stage Q into its own region
#pragma unroll
    for (int j = 0; j < 4; j++) {
        int idx = tid + j * 128;
        int r = idx >> 2, c4 = idx & 3;
        *(uint4*)(asmem + r * KSTR_U + c4 * 4) = *(const uint4*)(Qb + r * RANK + c4 * 8);
    }
    CP_WAIT(2);            // tile 0 landed
    __syncthreads();       // Q staged + tile 0 visible

    uint32_t qf[2][2][4];   // [mt][k16-step][frag]
#pragma unroll
    for (int mt = 0; mt < 2; mt++)
#pragma unroll
        for (int ks = 0; ks < 2; ks++) {
            const uint32_t* p = asmem + (wq + mt * 16 + g) * KSTR_U + ks * 8 + t;
            qf[mt][ks][0] = p[0];
            qf[mt][ks][1] = p[8 * KSTR_U];
            qf[mt][ks][2] = p[4];
            qf[mt][ks][3] = p[8 * KSTR_U + 4];
        }

    float l[4];
    float oacc[2][4][4];
#pragma unroll
    for (int i = 0; i < 4; i++) l[i] = 0.f;
#pragma unroll
    for (int mt = 0; mt < 2; mt++)
#pragma unroll
        for (int nt = 0; nt < 4; nt++)
#pragma unroll
            for (int e = 0; e < 4; e++) oacc[mt][nt][e] = 0.f;

    // S for tile 0 (prologue)
    float sacc[2][8][4];
    s_mma_tile(sacc, qf, asmem + AKV_OFF, g, t);

    for (int kt = 0; kt < NKT; kt++) {
        // ---- softmax: drain sacc -> ph (packed fp16), accumulate l ----
        uint32_t ph[2][8][2];
#pragma unroll
        for (int mt = 0; mt < 2; mt++) {
#pragma unroll
            for (int nt = 0; nt < 8; nt++) {
                uint32_t s01 = pack_h2(sacc[mt][nt][0], sacc[mt][nt][1]);
                uint32_t s23 = pack_h2(sacc[mt][nt][2], sacc[mt][nt][3]);
                uint32_t p01 = ex2_h2(s01);
                uint32_t p23 = ex2_h2(s23);
                float2 f01 = __half22float2(*(__half2*)&p01);
                float2 f23 = __half22float2(*(__half2*)&p23);
                l[mt * 2]     += f01.x + f01.y;
                l[mt * 2 + 1] += f23.x + f23.y;
                ph[mt][nt][0] = p01;
                ph[mt][nt][1] = p23;
            }
        }

        if (kt + 1 < NKT) {
            CP_WAIT(1);        // tile kt+1 landed (kt+2 may still be pending)
            __syncthreads();   // all warps past tile kt-1's V reads
            if (kt + 3 < NKT)
                prefetch_kv(sbase, (kt + 3) & 3, Kb, VTb, kt + 3, tid);
            // S-mma for tile kt+1 — independent of PV(kt), fills the pipe
            s_mma_tile(sacc, qf, asmem + AKV_OFF + ((kt + 1) & 3) * ASTG_U, g, t);
        }

        // ---- O += P V for tile kt ----
        const uint32_t* sVb = asmem + AKV_OFF + (kt & 3) * ASTG_U + AKSZ_U;
#pragma unroll
        for (int ks = 0; ks < 4; ks++) {
            uint32_t bf[4][2];
#pragma unroll
            for (int nt = 0; nt < 4; nt++) {
                const uint32_t* p = sVb + (nt * 8 + g) * VSTR_U + ks * 8 + t;
                bf[nt][0] = p[0];
                bf[nt][1] = p[4];
            }
#pragma unroll
            for (int mt = 0; mt < 2; mt++) {
                uint32_t af[4] = { ph[mt][2 * ks][0],     ph[mt][2 * ks][1],
                                   ph[mt][2 * ks + 1][0], ph[mt][2 * ks + 1][1] };
#pragma unroll
                for (int nt = 0; nt < 4; nt++)
                    mma_f16(oacc[mt][nt], af, bf[nt]);
            }
        }
    }

    // ---- epilogue: single l reduction, normalize, round fp16, store ----
#pragma unroll
    for (int i = 0; i < 4; i++) {
        l[i] += __shfl_xor_sync(0xffffffffu, l[i], 1);
        l[i] += __shfl_xor_sync(0xffffffffu, l[i], 2);
    }
    int b = bh >> 4, h = bh & 15;
#pragma unroll
    for (int mt = 0; mt < 2; mt++)
#pragma unroll
        for (int lh = 0; lh < 2; lh++) {
            int row = q0 + wq + mt * 16 + g + lh * 8;
            float inv = 1.f / l[mt * 2 + lh];
            __half* yp = g_yr + ((size_t)(b * SEQ) + row) * K_FOLD + h * RANK;
#pragma unroll
            for (int nt = 0; nt < 4; nt++) {
                uint32_t hv = pack_h2(oacc[mt][nt][lh * 2] * inv,
                                      oacc[mt][nt][lh * 2 + 1] * inv);
                *(uint32_t*)(yp + nt * 8 + 2 * t) = hv;
            }
        }
}

// ---------------- launch --------------------------------------------------
extern "C" void kernel_launch(void* const* d_in, const int* in_sizes, int n_in,
                              void* d_out, int out_size) {
    const float* x     = (const float*)d_in[0];
    const float* Wq    = (const float*)d_in[1];
    const float* Wk    = (const float*)d_in[2];
    const float* Wv    = (const float*)d_in[3];
    const float* Wo    = (const float*)d_in[4];
    const float* Wdown = (const float*)d_in[5];
    const float* Wup   = (const float*)d_in[6];
    float* out = (float*)d_out;

    void *pBq, *pBo, *pXc, *pYr;
    cudaGetSymbolAddress(&pBq, g_Bqkv);
    cudaGetSymbolAddress(&pBo, g_Bo);
    cudaGetSymbolAddress(&pXc, g_xc);
    cudaGetSymbolAddress(&pYr, g_yr);

    static bool attr_done = false;
    if (!attr_done) {
        cudaFuncSetAttribute(gemm_mma<0>, cudaFuncAttributeMaxDynamicSharedMemorySize, SMEM_BYTES);
        cudaFuncSetAttribute(gemm_mma<1>, cudaFuncAttributeMaxDynamicSharedMemorySize, SMEM_BYTES);
        cudaFuncSetAttribute(attn_mma,    cudaFuncAttributeMaxDynamicSharedMemorySize, ASMEM_BYTES);
        attr_done = true;
    }

    // fused prep: convert x + fold weights (one launch, independent blocks)
    prep_kernel<<<PREP_BLKS, 256>>>(x, Wq, Wk, Wv, Wo, Wdown, Wup);

    // q_r/k_r/v_r = x @ A_qkv  (fp16 mma.sync, scatter epilogue; q pre-scaled)
    gemm_mma<1><<<dim3(N_QKV/128, M_TOT/128), 128, SMEM_BYTES>>>(
        (const __half*)pXc, (const __half*)pBq, nullptr, N_QKV, D_MODEL);

    // rank-space fp16 tensor-core flash attention -> g_yr [4096, 512]
    attn_mma<<<dim3(SEQ/TQ, BATCH*N_HEADS), 128, ASMEM_BYTES>>>();

    // out = y_r @ B_o  (fp16 mma.sync)
    gemm_mma<0><<<dim3(D_MODEL/128, M_TOT/128), 128, SMEM_BYTES>>>(
        (const __half*)pYr, (const __half*)pBo, out, D_MODEL, K_FOLD);
}

// round 15
// speedup vs baseline: 1.0295x; 1.0090x over previous
#include <cuda_runtime.h>
#include <cuda_fp16.h>
#include <cstdint>
#include <cstddef>

#define D_MODEL 2048
#define N_HEADS 16
#define D_HEAD  128
#define RANK    32
#define BATCH   2
#define SEQ     2048
#define M_TOT   (BATCH*SEQ)        // 4096
#define N_QKV   (3*N_HEADS*RANK)   // 1536
#define K_FOLD  (N_HEADS*RANK)     // 512

// ---------------- device scratch (no allocations allowed) ----------------
__device__ __half g_Bqkv[(size_t)N_QKV * D_MODEL];   // [1536][2048] K-major fp16
__device__ __half g_Bo[(size_t)D_MODEL * K_FOLD];    // [2048][512]  K-major fp16
__device__ __half g_xc[(size_t)M_TOT * D_MODEL];     // fp16 x
__device__ __half g_qr[(size_t)BATCH * N_HEADS * SEQ * RANK];   // [bh][seq][r] (pre-scaled)
__device__ __half g_kr[(size_t)BATCH * N_HEADS * SEQ * RANK];   // [bh][seq][r]
__device__ __half g_vrT[(size_t)BATCH * N_HEADS * RANK * SEQ];  // [bh][r][seq]
__device__ __half g_yr[(size_t)M_TOT * K_FOLD];      // [4096][512] fp16

// ---------------- helpers -------------------------------------------------
__device__ __forceinline__ uint32_t smem_u32(const void* p) {
    uint32_t a;
    asm("{ .reg .u64 t; cvta.to.shared.u64 t, %1; cvt.u32.u64 %0, t; }"
        : "=r"(a) : "l"(p));
    return a;
}

__device__ __forceinline__ void cp_async16(uint32_t saddr, const void* gaddr) {
    asm volatile("cp.async.cg.shared.global [%0], [%1], 16;"
                 :: "r"(saddr), "l"(gaddr));
}
#define CP_COMMIT()  asm volatile("cp.async.commit_group;" ::: "memory")
#define CP_WAIT(n)   asm volatile("cp.async.wait_group %0;" :: "n"(n) : "memory")

// fp16 mma m16n8k16 row.col, fp32 accumulate
__device__ __forceinline__ void mma_f16(float* c, const uint32_t* a, const uint32_t* b) {
    asm volatile(
        "mma.sync.aligned.m16n8k16.row.col.f32.f16.f16.f32 "
        "{%0,%1,%2,%3}, {%4,%5,%6,%7}, {%8,%9}, {%0,%1,%2,%3};"
        : "+f"(c[0]), "+f"(c[1]), "+f"(c[2]), "+f"(c[3])
        : "r"(a[0]), "r"(a[1]), "r"(a[2]), "r"(a[3]), "r"(b[0]), "r"(b[1]));
}

__device__ __forceinline__ uint32_t pack_h2(float a, float b) {
    __half2 h = __floats2half2_rn(a, b);
    return *(uint32_t*)&h;
}

// packed fp16x2 exp2 — one MUFU op for two elements
__device__ __forceinline__ uint32_t ex2_h2(uint32_t h2in) {
    uint32_t r;
    asm("ex2.approx.f16x2 %0, %1;" : "=r"(r) : "r"(h2in));
    return r;
}

// (1/sqrt(32)) * log2(e) — folded into q at the GEMM1 epilogue
#define SC2F 0.25503837897544185f

// ---------------- fused prep: convert x + fold weights --------------------
#define PREP_CONV_BLKS 4096
#define PREP_QKV_BLKS  384
#define PREP_OUT_BLKS  128
#define PREP_BLKS (PREP_CONV_BLKS + PREP_QKV_BLKS + PREP_OUT_BLKS)

__global__ void __launch_bounds__(256)
prep_kernel(const float* __restrict__ x,
            const float* __restrict__ Wq, const float* __restrict__ Wk,
            const float* __restrict__ Wv, const float* __restrict__ Wo,
            const float* __restrict__ Wdown, const float* __restrict__ Wup) {
    __shared__ float sW[D_HEAD * RANK];   // 16 KB, used by fold tasks
    int tid = threadIdx.x;
    int bid = blockIdx.x;

    if (bid < PREP_CONV_BLKS) {
        // ---- convert x to fp16 ----
        int i = bid * 256 + tid;          // uint4 index
        const float4* xf = (const float4*)x;
        float4 v0 = xf[i * 2], v1 = xf[i * 2 + 1];
        uint4 o;
        o.x = pack_h2(v0.x, v0.y); o.y = pack_h2(v0.z, v0.w);
        o.z = pack_h2(v1.x, v1.y); o.w = pack_h2(v1.z, v1.w);
        ((uint4*)g_xc)[i] = o;
        return;
    }

    if (bid < PREP_CONV_BLKS + PREP_QKV_BLKS) {
        // ---- fold Wq/Wk/Wv with Wdown (K-major out, fp16) ----
        int b2 = bid - PREP_CONV_BLKS;
        int w  = b2 >> 7;                 // 0..2
        int h  = (b2 >> 3) & 15;
        int d  = (b2 & 7) * 256 + tid;

        for (int i = tid; i < D_HEAD*RANK/4; i += 256)
            ((float4*)sW)[i] = ((const float4*)Wdown)[i];
        __syncthreads();

        const float* W = (w == 0) ? Wq : (w == 1) ? Wk : Wv;
        const float* wp = W + (size_t)h * D_HEAD * D_MODEL + d;

        float acc[RANK];
#pragma unroll
        for (int r = 0; r < RANK; r++) acc[r] = 0.f;
#pragma unroll 4
        for (int i = 0; i < D_HEAD; i++) {
            float wv = wp[(size_t)i * D_MODEL];
#pragma unroll
            for (int r = 0; r < RANK; r++) acc[r] += wv * sW[i * RANK + r];
        }
#pragma unroll
        for (int r = 0; r < RANK; r++)
            g_Bqkv[(size_t)(w * K_FOLD + h * RANK + r) * D_MODEL + d] = __float2half_rn(acc[r]);
        return;
    }

    {
        // ---- fold Wup with Wo (K-major out [j][h*32+r], fp16) ----
        int b3 = bid - PREP_CONV_BLKS - PREP_QKV_BLKS;
        int h  = b3 >> 3;
        int j  = (b3 & 7) * 256 + tid;

        for (int i = tid; i < RANK*D_HEAD/4; i += 256)
            ((float4*)sW)[i] = ((const float4*)Wup)[i];
        __syncthreads();

        const float* wop = Wo + (size_t)j * D_MODEL + h * D_HEAD;

        float acc[RANK];
#pragma unroll
        for (int r = 0; r < RANK; r++) acc[r] = 0.f;
#pragma unroll 2
        for (int i = 0; i < D_HEAD; i += 4) {
            float4 w4 = *(const float4*)(wop + i);
#pragma unroll
            for (int r = 0; r < RANK; r++)
                acc[r] += w4.x * sW[r * D_HEAD + i]     + w4.y * sW[r * D_HEAD + i + 1]
                        + w4.z * sW[r * D_HEAD + i + 2] + w4.w * sW[r * D_HEAD + i + 3];
        }
#pragma unroll
        for (int r = 0; r < RANK; r++)
            g_Bo[(size_t)j * K_FOLD + h * RANK + r] = __float2half_rn(acc[r]);
    }
}

// ---------------- fp16 mma.sync GEMM (4 warps, 64x64 warp tiles) ----------
#define SSTR_U 36                             // b32 units per smem row (32 data)
#define ABUF_U (128 * SSTR_U)                 // 4608
#define STAGE_U (2 * ABUF_U)                  // 9216
#define GSTAGES 3
#define SMEM_BYTES (GSTAGES * STAGE_U * 4)    // 110592

template <int EPI>
__global__ void __launch_bounds__(128, 2)
gemm_mma(const __half* __restrict__ A, const __half* __restrict__ B,
         float* __restrict__ C, int N, int K) {
    extern __shared__ uint32_t smem_u[];
    uint32_t sbase = smem_u32(smem_u);

    int tid = threadIdx.x;
    int lane = tid & 31, wid = tid >> 5;
    int g = lane >> 2, t = lane & 3;
    int wm = (wid >> 1) * 64;
    int wn = (wid & 1) * 64;
    int m0 = blockIdx.y * 128;
    int n0 = blockIdx.x * 128;

    const __half* ga[8];
    const __half* gb[8];
    uint32_t sa_off[8], sb_off[8];
#pragma unroll
    for (int i = 0; i < 8; i++) {
        int idx = tid + i * 128;
        int r  = idx >> 3;
        int c4 = idx & 7;
        ga[i] = A + (size_t)(m0 + r) * K + c4 * 8;
        gb[i] = B + (size_t)(n0 + r) * K + c4 * 8;
        sa_off[i] = (uint32_t)((r * SSTR_U + c4 * 4) * 4);
        sb_off[i] = (uint32_t)((ABUF_U + r * SSTR_U + c4 * 4) * 4);
    }

    float acc[4][8][4];
#pragma unroll
    for (int mt = 0; mt < 4; mt++)
#pragma unroll
        for (int nt = 0; nt < 8; nt++)
#pragma unroll
            for (int e = 0; e < 4; e++) acc[mt][nt][e] = 0.f;

    int nk = K >> 6;   // K chunks of 64

#pragma unroll
    for (int s = 0; s < 2; s++) {
        uint32_t bofs = sbase + s * (STAGE_U * 4);
        const int ko = s * 64;
#pragma unroll
        for (int i = 0; i < 8; i++) {
            cp_async16(bofs + sa_off[i], ga[i] + ko);
            cp_async16(bofs + sb_off[i], gb[i] + ko);
        }
        CP_COMMIT();
    }

    int cur = 0, pre = 2;
    for (int kc = 0; kc < nk; kc++) {
        if (kc + 1 < nk) { CP_WAIT(1); } else { CP_WAIT(0); }
        __syncthreads();

        if (kc + 2 < nk) {
            uint32_t bofs = sbase + pre * (STAGE_U * 4);
            const int ko = (kc + 2) * 64;
#pragma unroll
            for (int i = 0; i < 8; i++) {
                cp_async16(bofs + sa_off[i], ga[i] + ko);
                cp_async16(bofs + sb_off[i], gb[i] + ko);
            }
            CP_COMMIT();
        }

        const uint32_t* sA = smem_u + cur * STAGE_U;
        const uint32_t* sB = sA + ABUF_U;

#pragma unroll
        for (int ks = 0; ks < 4; ks++) {      // 4 x k16
            int p0 = ks * 8;
            uint32_t a[4][4], b[8][2];
#pragma unroll
            for (int mt = 0; mt < 4; mt++) {
                const uint32_t* p = sA + (wm + mt * 16 + g) * SSTR_U + p0 + t;
                a[mt][0] = p[0];
                a[mt][1] = p[8 * SSTR_U];
                a[mt][2] = p[4];
                a[mt][3] = p[8 * SSTR_U + 4];
            }
#pragma unroll
            for (int nt = 0; nt < 8; nt++) {
                const uint32_t* p = sB + (wn + nt * 8 + g) * SSTR_U + p0 + t;
                b[nt][0] = p[0];
                b[nt][1] = p[4];
            }
#pragma unroll
            for (int mt = 0; mt < 4; mt++)
#pragma unroll
                for (int nt = 0; nt < 8; nt++)
                    mma_f16(acc[mt][nt], a[mt], b[nt]);
        }
        cur = (cur == GSTAGES - 1) ? 0 : cur + 1;
        pre = (pre == GSTAGES - 1) ? 0 : pre + 1;
    }

#pragma unroll
    for (int mt = 0; mt < 4; mt++) {
        int r0 = m0 + wm + mt * 16 + g;
#pragma unroll
        for (int nt = 0; nt < 8; nt++) {
            int cn = n0 + wn + nt * 8 + t * 2;
            if (EPI == 0) {
                *(float2*)(C + (size_t)r0 * N + cn) =
                    make_float2(acc[mt][nt][0], acc[mt][nt][1]);
                *(float2*)(C + (size_t)(r0 + 8) * N + cn) =
                    make_float2(acc[mt][nt][2], acc[mt][nt][3]);
            } else {
                // scatter q/k/v as fp16 (q pre-scaled by SC2F; V transposed)
                int w = cn >> 9;
                int h = (cn >> 5) & 15;
                int r = cn & 31;
#pragma unroll
                for (int lh = 0; lh < 2; lh++) {
                    int rr = r0 + lh * 8;
                    int b0 = rr >> 11, t0 = rr & 2047;
                    float v0 = acc[mt][nt][lh * 2], v1 = acc[mt][nt][lh * 2 + 1];
                    if (w == 2) {
                        __half* vp = g_vrT + ((size_t)(b0 * N_HEADS + h) * RANK) * SEQ + t0;
                        vp[(size_t)r * SEQ]       = __float2half_rn(v0);
                        vp[(size_t)(r + 1) * SEQ] = __float2half_rn(v1);
                    } else {
                        if (w == 0) { v0 *= SC2F; v1 *= SC2F; }
                        __half* basep = (w == 0) ? g_qr : g_kr;
                        uint32_t hv = pack_h2(v0, v1);
                        *(uint32_t*)(basep + ((size_t)(b0 * N_HEADS + h) * SEQ + t0) * RANK + r) = hv;
                    }
                }
            }
        }
    }
}

// ---------------- fp16 tensor-core flash attention in rank space ----------
// R12 loop (3-stage ring, 128 thr, 32 q-rows/warp) + TENSOR-CORE l:
// a 5th PV n-tile against a constant ones-column computes l = sum_k P[.,k]
// in an mma fp32 accumulator, deleting all H2F converts and l-FADD chains
// from softmax (which shrinks to pack+ex2 per fragment).
#define TQ   128
#define TK   64
#define NKT  (SEQ/TK)       // 32
#define KSTR_U 20           // K row: 16 b32 data (32 halves)
#define VSTR_U 36           // V_T row: 32 b32 data (64 halves)
#define QSTG_U (128*KSTR_U) // 2560 (Q staging)
#define ONES_OFF QSTG_U
#define ONES_U  (8*VSTR_U)  // 288: 8 "V rows" x 64 halves (row 0 = ones)
#define AKV_OFF (ONES_OFF + ONES_U)   // 2848
#define AKSZ_U (TK*KSTR_U)  // 1280
#define AVSZ_U (32*VSTR_U)  // 1152
#define ASTG_U (AKSZ_U+AVSZ_U)  // 2432
#define ASTAGES 3
#define ASMEM_BYTES ((AKV_OFF + ASTAGES*ASTG_U)*4)   // 40576

__device__ __forceinline__ void prefetch_kv(uint32_t sbase, int stage,
                                            const __half* Kb, const __half* VTb,
                                            int kt, int tid) {
    uint32_t koff = sbase + (AKV_OFF + stage * ASTG_U) * 4;
    uint32_t voff = koff + AKSZ_U * 4;
    const __half* kp = Kb + (size_t)kt * TK * RANK;
    const __half* vp = VTb + kt * TK;
#pragma unroll
    for (int j = 0; j < 2; j++) {           // K: 64 rows x 4 chunks = 256
        int idx = tid + j * 128;
        int r = idx >> 2, c4 = idx & 3;
        cp_async16(koff + (r * KSTR_U + c4 * 4) * 4, kp + r * RANK + c4 * 8);
    }
#pragma unroll
    for (int j = 0; j < 2; j++) {           // V_T: 32 rows x 8 chunks = 256
        int idx = tid + j * 128;
        int r = idx >> 3, c4 = idx & 7;
        cp_async16(voff + (r * VSTR_U + c4 * 4) * 4, vp + (size_t)r * SEQ + c4 * 8);
    }
    CP_COMMIT();
}

__global__ void __launch_bounds__(128, 2)
attn_mma() {
    extern __shared__ uint32_t asmem[];
    uint32_t sbase = smem_u32(asmem);
    int tid = threadIdx.x;
    int lane = tid & 31, wid = tid >> 5;
    int g = lane >> 2, t = lane & 3;
    int bh = blockIdx.y;
    int q0 = blockIdx.x * TQ;
    int wq = wid * 32;

    const __half* Qb  = g_qr + ((size_t)bh * SEQ + q0) * RANK;
    const __half* Kb  = g_kr + (size_t)bh * SEQ * RANK;
    const __half* VTb = g_vrT + (size_t)bh * RANK * SEQ;

    prefetch_kv(sbase, 0, Kb, VTb, 0, tid);
    prefetch_kv(sbase, 1, Kb, VTb, 1, tid);

    // stage Q + init the ones block (row 0 of the extra V tile = fp16 1.0)
#pragma unroll
    for (int j = 0; j < 4; j++) {
        int idx = tid + j * 128;
        int r = idx >> 2, c4 = idx & 3;
        *(uint4*)(asmem + r * KSTR_U + c4 * 4) = *(const uint4*)(Qb + r * RANK + c4 * 8);
    }
    for (int i = tid; i < ONES_U; i += 128) {
        int r2 = i / VSTR_U;
        asmem[ONES_OFF + i] = (r2 == 0) ? 0x3C003C00u : 0u;
    }
    __syncthreads();

    uint32_t qf[2][2][4];   // [mt][k16-step][frag]
#pragma unroll
    for (int mt = 0; mt < 2; mt++)
#pragma unroll
        for (int ks = 0; ks < 2; ks++) {
            const uint32_t* p = asmem + (wq + mt * 16 + g) * KSTR_U + ks * 8 + t;
            qf[mt][ks][0] = p[0];
            qf[mt][ks][1] = p[8 * KSTR_U];
            qf[mt][ks][2] = p[4];
            qf[mt][ks][3] = p[8 * KSTR_U + 4];
        }

    float oacc[2][4][4];
    float lacc[2][4];       // l tile: col 0 (t=0) carries sum_k P
#pragma unroll
    for (int mt = 0; mt < 2; mt++) {
#pragma unroll
        for (int nt = 0; nt < 4; nt++)
#pragma unroll
            for (int e = 0; e < 4; e++) oacc[mt][nt][e] = 0.f;
#pragma unroll
        for (int e = 0; e < 4; e++) lacc[mt][e] = 0.f;
    }

    const uint32_t* sOnes = asmem + ONES_OFF;

    int cur = 0, pre = 2;
    for (int kt = 0; kt < NKT; kt++) {
        if (kt + 1 < NKT) { CP_WAIT(1); } else { CP_WAIT(0); }
        __syncthreads();

        if (kt + 2 < NKT) prefetch_kv(sbase, pre, Kb, VTb, kt + 2, tid);

        const uint32_t* sKb = asmem + AKV_OFF + cur * ASTG_U;
        const uint32_t* sVb = sKb + AKSZ_U;

        // ---- S = Q K^T (q pre-scaled: S already in log2 domain) ----
        float sacc[2][8][4];
#pragma unroll
        for (int mt = 0; mt < 2; mt++)
#pragma unroll
            for (int nt = 0; nt < 8; nt++)
#pragma unroll
                for (int e = 0; e < 4; e++) sacc[mt][nt][e] = 0.f;
#pragma unroll
        for (int ks = 0; ks < 2; ks++) {
            uint32_t bk[8][2];
#pragma unroll
            for (int nt = 0; nt < 8; nt++) {
                const uint32_t* p = sKb + (nt * 8 + g) * KSTR_U + ks * 8 + t;
                bk[nt][0] = p[0];
                bk[nt][1] = p[4];
            }
#pragma unroll
            for (int mt = 0; mt < 2; mt++)
#pragma unroll
                for (int nt = 0; nt < 8; nt++)
                    mma_f16(sacc[mt][nt], qf[mt][ks], bk[nt]);
        }

        // ---- P = exp2(S): pack + f16x2 MUFU only (no l bookkeeping) ----
        uint32_t ph[2][8][2];
#pragma unroll
        for (int mt = 0; mt < 2; mt++) {
#pragma unroll
            for (int nt = 0; nt < 8; nt++) {
                ph[mt][nt][0] = ex2_h2(pack_h2(sacc[mt][nt][0], sacc[mt][nt][1]));
                ph[mt][nt][1] = ex2_h2(pack_h2(sacc[mt][nt][2], sacc[mt][nt][3]));
            }
        }

        // ---- O += P V ; l += P @ ones (5th n-tile, fp32 mma accum) ----
#pragma unroll
        for (int ks = 0; ks < 4; ks++) {
            uint32_t bf[4][2];
#pragma unroll
            for (int nt = 0; nt < 4; nt++) {
                const uint32_t* p = sVb + (nt * 8 + g) * VSTR_U + ks * 8 + t;
                bf[nt][0] = p[0];
                bf[nt][1] = p[4];
            }
            const uint32_t* po = sOnes + g * VSTR_U + ks * 8 + t;
            uint32_t bo[2] = { po[0], po[4] };
#pragma unroll
            for (int mt = 0; mt < 2; mt++) {
                uint32_t af[4] = { ph[mt][2 * ks][0],     ph[mt][2 * ks][1],
                                   ph[mt][2 * ks + 1][0], ph[mt][2 * ks + 1][1] };
#pragma unroll
                for (int nt = 0; nt < 4; nt++)
                    mma_f16(oacc[mt][nt], af, bf[nt]);
                mma_f16(lacc[mt], af, bo);
            }
        }
        cur = (cur == ASTAGES - 1) ? 0 : cur + 1;
        pre = (pre == ASTAGES - 1) ? 0 : pre + 1;
    }

    // ---- epilogue: l lives in lane t=0 (col 0); broadcast, normalize ----
    int src = lane & ~3;   // lane g*4 (t = 0)
    int b = bh >> 4, h = bh & 15;
#pragma unroll
    for (int mt = 0; mt < 2; mt++) {
        float lv0 = __shfl_sync(0xffffffffu, lacc[mt][0], src);   // row g
        float lv1 = __shfl_sync(0xffffffffu, lacc[mt][2], src);   // row g+8
#pragma unroll
        for (int lh = 0; lh < 2; lh++) {
            int row = q0 + wq + mt * 16 + g + lh * 8;
            float inv = 1.f / (lh == 0 ? lv0 : lv1);
            __half* yp = g_yr + ((size_t)(b * SEQ) + row) * K_FOLD + h * RANK;
#pragma unroll
            for (int nt = 0; nt < 4; nt++) {
                uint32_t hv = pack_h2(oacc[mt][nt][lh * 2] * inv,
                                      oacc[mt][nt][lh * 2 + 1] * inv);
                *(uint32_t*)(yp + nt * 8 + 2 * t) = hv;
            }
        }
    }
}

// ---------------- launch --------------------------------------------------
extern "C" void kernel_launch(void* const* d_in, const int* in_sizes, int n_in,
                              void* d_out, int out_size) {
    const float* x     = (const float*)d_in[0];
    const float* Wq    = (const float*)d_in[1];
    const float* Wk    = (const float*)d_in[2];
    const float* Wv    = (const float*)d_in[3];
    const float* Wo    = (const float*)d_in[4];
    const float* Wdown = (const float*)d_in[5];
    const float* Wup   = (const float*)d_in[6];
    float* out = (float*)d_out;

    void *pBq, *pBo, *pXc, *pYr;
    cudaGetSymbolAddress(&pBq, g_Bqkv);
    cudaGetSymbolAddress(&pBo, g_Bo);
    cudaGetSymbolAddress(&pXc, g_xc);
    cudaGetSymbolAddress(&pYr, g_yr);

    static bool attr_done = false;
    if (!attr_done) {
        cudaFuncSetAttribute(gemm_mma<0>, cudaFuncAttributeMaxDynamicSharedMemorySize, SMEM_BYTES);
        cudaFuncSetAttribute(gemm_mma<1>, cudaFuncAttributeMaxDynamicSharedMemorySize, SMEM_BYTES);
        cudaFuncSetAttribute(attn_mma,    cudaFuncAttributeMaxDynamicSharedMemorySize, ASMEM_BYTES);
        attr_done = true;
    }

    // fused prep: convert x + fold weights (one launch, independent blocks)
    prep_kernel<<<PREP_BLKS, 256>>>(x, Wq, Wk, Wv, Wo, Wdown, Wup);

    // q_r/k_r/v_r = x @ A_qkv  (fp16 mma.sync, scatter epilogue; q pre-scaled)
    gemm_mma<1><<<dim3(N_QKV/128, M_TOT/128), 128, SMEM_BYTES>>>(
        (const __half*)pXc, (const __half*)pBq, nullptr, N_QKV, D_MODEL);

    // rank-space fp16 tensor-core flash attention -> g_yr [4096, 512]
    attn_mma<<<dim3(SEQ/TQ, BATCH*N_HEADS), 128, ASMEM_BYTES>>>();

    // out = y_r @ B_o  (fp16 mma.sync)
    gemm_mma<0><<<dim3(D_MODEL/128, M_TOT/128), 128, SMEM_BYTES>>>(
        (const __half*)pYr, (const __half*)pBo, out, D_MODEL, K_FOLD);
}